// round 1
// baseline (speedup 1.0000x reference)
#include <cuda_runtime.h>
#include <cstdint>

#define NB 2048
#define NC 9605
#define TPB 256
#define TOPK 10

__global__ void zero_out_kernel(float* out) { out[0] = 0.0f; }

__device__ __forceinline__ unsigned ordkey(float v) {
    unsigned u = __float_as_uint(v);
    return (u & 0x80000000u) ? ~u : (u | 0x80000000u);
}

// base (log term) and focal weight w for one element
__device__ __forceinline__ void elem_base_w(float xv, float yv, float& base, float& w) {
    float e  = __expf(-xv);
    float p  = __fdividef(1.0f, 1.0f + e);              // sigmoid(x)
    float pn = fminf(1.0f - p + 0.05f, 1.0f);           // xs_neg
    if (yv > 0.0f) {
        base = __logf(fmaxf(p, 1e-8f));
        w    = 1.0f - p;                                 // (1-pt)^1
    } else {
        base = __logf(fmaxf(pn, 1e-8f));
        float t  = 1.0f - pn;                            // (1-pt)
        float t2 = t * t;
        w = t2 * t2;                                     // (1-pt)^4
    }
}

__global__ __launch_bounds__(TPB)
void asl_loss_kernel(const float* __restrict__ x, const float* __restrict__ y,
                     const int* __restrict__ compost_idx,
                     const int* __restrict__ recycle_idx,
                     const int* __restrict__ donate_idx,
                     const int* __restrict__ wl_map,
                     float* __restrict__ out)
{
    const int row = blockIdx.x;
    const int tid = threadIdx.x;
    const float* __restrict__ xr = x + (size_t)row * NC;
    const float* __restrict__ yr = y + (size_t)row * NC;

    __shared__ int hasF[3];
    __shared__ unsigned long long keys[TPB * TOPK];   // 20 KB
    __shared__ float red[TPB];

    if (tid < 3) hasF[tid] = 0;
    __syncthreads();
    // per-row whitelist-group presence flags (benign shared races; write only 1)
    if (tid < 30)       { if (yr[compost_idx[tid]]        > 0.0f) hasF[0] = 1; }
    else if (tid < 100) { if (yr[recycle_idx[tid - 30]]   > 0.0f) hasF[1] = 1; }
    else if (tid < 170) { if (yr[donate_idx[tid - 100]]   > 0.0f) hasF[2] = 1; }

    // thread-local sorted (descending) top-10 keys + base*w partial sum
    unsigned long long top[TOPK];
#pragma unroll
    for (int i = 0; i < TOPK; i++) top[i] = 0ull;
    float acc = 0.0f;

#pragma unroll 2
    for (int c = tid; c < NC; c += TPB) {
        float xv = xr[c];
        float yv = yr[c];
        float base, w;
        elem_base_w(xv, yv, base, w);
        acc += base * w;
        // top-k ordering by x (sigmoid monotone => same order as xs_pos);
        // ~c in low bits => lower index wins ties, matching jax top_k
        unsigned long long key =
            ((unsigned long long)ordkey(xv) << 32) | (unsigned)(~(unsigned)c);
        if (key > top[TOPK - 1]) {
            int i = TOPK - 1;
#pragma unroll
            for (int k = 0; k < TOPK - 1; k++) {
                if (i > 0 && top[i - 1] < key) { top[i] = top[i - 1]; --i; }
            }
            top[i] = key;
        }
    }

#pragma unroll
    for (int i = 0; i < TOPK; i++) keys[tid * TOPK + i] = top[i];
    red[tid] = acc;
    __syncthreads();

    // tree merge of sorted top-10 lists + block sum reduction
    for (int s = TPB / 2; s >= 1; s >>= 1) {
        if (tid < s) {
            unsigned long long m[TOPK];
            unsigned long long* A  = &keys[tid * TOPK];
            unsigned long long* Bp = &keys[(tid + s) * TOPK];
            int ia = 0, ib = 0;
#pragma unroll
            for (int i = 0; i < TOPK; i++) {
                unsigned long long av = A[ia], bv = Bp[ib];
                if (av >= bv) { m[i] = av; ++ia; }
                else          { m[i] = bv; ++ib; }
            }
#pragma unroll
            for (int i = 0; i < TOPK; i++) A[i] = m[i];
            red[tid] += red[tid + s];
        }
        __syncthreads();
    }

    if (tid == 0) {
        const bool h1 = hasF[0] != 0, h2 = hasF[1] != 0, h3 = hasF[2] != 0;
        const bool gt4 = !(h1 | h2 | h3);
        bool found = false;
        float multf[TOPK];
        int   idxs[TOPK];
        // sequential scan over the 10 ranks (order matters via `found`)
#pragma unroll
        for (int r = 0; r < TOPK; r++) {
            int j = (int)(~(unsigned)keys[r]);
            idxs[r] = j;
            int wl = wl_map[j];
            bool in_map = wl > 0;
            bool in_gt = (wl == 1 && h1) || (wl == 2 && h2) ||
                         (wl == 3 && h3) || (wl == 4 && gt4);
            float f = (in_map && gt4) ? 0.5f : 1.0f;
            if (in_map && !in_gt && !found) f *= 2.0f;
            multf[r] = f;
            found = found || (in_map && in_gt);
        }
        const float extra = found ? 1.0f : 2.0f;
        float corr = 0.0f;
#pragma unroll
        for (int r = 0; r < TOPK; r++) {
            float f = multf[r] * extra;
            if (f != 1.0f) {
                int j = idxs[r];
                float base, w;
                elem_base_w(xr[j], yr[j], base, w);
                corr += base * w * (f - 1.0f);
            }
        }
        atomicAdd(out, -(red[0] + corr));
    }
}

extern "C" void kernel_launch(void* const* d_in, const int* in_sizes, int n_in,
                              void* d_out, int out_size)
{
    const float* x            = (const float*)d_in[0];
    const float* y            = (const float*)d_in[1];
    const int*   compost_idx  = (const int*)d_in[2];
    const int*   recycle_idx  = (const int*)d_in[3];
    const int*   donate_idx   = (const int*)d_in[4];
    const int*   wl_map       = (const int*)d_in[5];
    float*       out          = (float*)d_out;

    zero_out_kernel<<<1, 1>>>(out);
    asl_loss_kernel<<<NB, TPB>>>(x, y, compost_idx, recycle_idx, donate_idx,
                                 wl_map, out);
}

// round 2
// speedup vs baseline: 2.4937x; 2.4937x over previous
#include <cuda_runtime.h>
#include <cstdint>

#define NB 2048
#define NC 9605
#define TPB 256
#define TOPK 10

typedef unsigned long long u64;

__global__ void zero_out_kernel(float* out) { out[0] = 0.0f; }

__device__ __forceinline__ unsigned ordkey(float v) {
    unsigned u = __float_as_uint(v);
    return (u & 0x80000000u) ? ~u : (u | 0x80000000u);
}

// base*w for one element (gamma_pos=1, gamma_neg=4, clip=0.05)
__device__ __forceinline__ float elem_bw(float xv, float yv) {
    float e = __expf(-xv);
    float s = 1.0f + e;
    float r = __fdividef(1.0f, s);          // p = sigmoid(x)
    float base, w;
    if (yv > 0.0f) {
        base = __logf(fmaxf(r, 1e-8f));
        w = 1.0f - r;                        // (1-pt)^1
    } else {
        float pn = fminf(1.05f - r, 1.0f);   // xs_neg, >= 0.05 so no eps clamp
        base = __logf(pn);
        float t = fmaxf(r - 0.05f, 0.0f);    // 1 - pn
        float t2 = t * t;
        w = t2 * t2;                         // (1-pt)^4
    }
    return base * w;
}

// insert key into descending sorted t[0..9]; all-constant indices -> registers
__device__ __forceinline__ void insert10(u64 (&t)[TOPK], u64 key) {
    if (key > t[TOPK - 1]) {
        t[TOPK - 1] = key;
#pragma unroll
        for (int i = TOPK - 1; i > 0; --i) {
            u64 a = t[i - 1], b = t[i];
            t[i - 1] = a > b ? a : b;
            t[i]     = a > b ? b : a;
        }
    }
}

// merge two descending sorted 10-lists -> top-10 into a (register-only bitonic)
__device__ __forceinline__ void merge10(u64 (&a)[TOPK], const u64 (&b)[TOPK]) {
    u64 c[16];
#pragma unroll
    for (int i = 0; i < 16; ++i) {
        u64 av = (i < TOPK) ? a[i] : 0ull;
        u64 bv = (15 - i < TOPK) ? b[15 - i] : 0ull;
        c[i] = av > bv ? av : bv;            // halver: c holds top-16, bitonic
    }
#pragma unroll
    for (int d = 8; d >= 1; d >>= 1) {       // Batcher bitonic clean (desc)
#pragma unroll
        for (int i = 0; i < 16; ++i) {
            if ((i & d) == 0) {
                u64 u = c[i], v = c[i + d];
                c[i]     = u > v ? u : v;
                c[i + d] = u > v ? v : u;
            }
        }
    }
#pragma unroll
    for (int i = 0; i < TOPK; ++i) a[i] = c[i];
}

__global__ __launch_bounds__(TPB)
void asl_loss_kernel(const float* __restrict__ x, const float* __restrict__ y,
                     const int* __restrict__ compost_idx,
                     const int* __restrict__ recycle_idx,
                     const int* __restrict__ donate_idx,
                     const int* __restrict__ wl_map,
                     float* __restrict__ out)
{
    const int row = blockIdx.x;
    const int tid = threadIdx.x;
    const int wid = tid >> 5;
    const int lid = tid & 31;
    const float* __restrict__ xr = x + (size_t)row * NC;
    const float* __restrict__ yr = y + (size_t)row * NC;

    __shared__ int  hasF[3];
    __shared__ u64  wkeys[8][TOPK];
    __shared__ float wacc[8];

    if (tid < 3) hasF[tid] = 0;
    __syncthreads();
    if (tid < 30)       { if (yr[compost_idx[tid]]      > 0.0f) hasF[0] = 1; }
    else if (tid < 100) { if (yr[recycle_idx[tid - 30]] > 0.0f) hasF[1] = 1; }
    else if (tid < 170) { if (yr[donate_idx[tid - 100]] > 0.0f) hasF[2] = 1; }

    u64 top[TOPK];
#pragma unroll
    for (int i = 0; i < TOPK; ++i) top[i] = 0ull;
    float acc = 0.0f;

    // per-row float4 alignment fixup (NC=9605 rotates base alignment mod 16B)
    const int mis  = (int)(((uintptr_t)xr & 15u) >> 2);
    const int pre  = (4 - mis) & 3;
    const int n4   = (NC - pre) >> 2;
    const int tail_start = pre + (n4 << 2);
    const int tail = NC - tail_start;

    if (tid < pre) {
        int c = tid;
        acc += elem_bw(xr[c], yr[c]);
        insert10(top, ((u64)ordkey(xr[c]) << 32) | (unsigned)(~(unsigned)c));
    }
    if (tid < tail) {
        int c = tail_start + tid;
        acc += elem_bw(xr[c], yr[c]);
        insert10(top, ((u64)ordkey(xr[c]) << 32) | (unsigned)(~(unsigned)c));
    }

    const float4* __restrict__ x4 = (const float4*)(xr + pre);
    const float4* __restrict__ y4 = (const float4*)(yr + pre);
#pragma unroll 2
    for (int k = tid; k < n4; k += TPB) {
        float4 xv = x4[k];
        float4 yv = y4[k];
        int c = pre + (k << 2);
        acc += elem_bw(xv.x, yv.x);
        insert10(top, ((u64)ordkey(xv.x) << 32) | (unsigned)(~(unsigned)(c)));
        acc += elem_bw(xv.y, yv.y);
        insert10(top, ((u64)ordkey(xv.y) << 32) | (unsigned)(~(unsigned)(c + 1)));
        acc += elem_bw(xv.z, yv.z);
        insert10(top, ((u64)ordkey(xv.z) << 32) | (unsigned)(~(unsigned)(c + 2)));
        acc += elem_bw(xv.w, yv.w);
        insert10(top, ((u64)ordkey(xv.w) << 32) | (unsigned)(~(unsigned)(c + 3)));
    }

    // intra-warp butterfly merge (all in registers)
#pragma unroll
    for (int off = 16; off >= 1; off >>= 1) {
        u64 other[TOPK];
#pragma unroll
        for (int i = 0; i < TOPK; ++i)
            other[i] = __shfl_xor_sync(0xFFFFFFFFu, top[i], off);
        merge10(top, other);
        acc += __shfl_xor_sync(0xFFFFFFFFu, acc, off);
    }
    if (lid == 0) {
#pragma unroll
        for (int i = 0; i < TOPK; ++i) wkeys[wid][i] = top[i];
        wacc[wid] = acc;
    }
    __syncthreads();

    if (wid == 0) {
        u64 t2[TOPK];
        float a2 = (lid < 8) ? wacc[lid] : 0.0f;
#pragma unroll
        for (int i = 0; i < TOPK; ++i) t2[i] = (lid < 8) ? wkeys[lid][i] : 0ull;
#pragma unroll
        for (int off = 4; off >= 1; off >>= 1) {
            u64 other[TOPK];
#pragma unroll
            for (int i = 0; i < TOPK; ++i)
                other[i] = __shfl_xor_sync(0xFFFFFFFFu, t2[i], off);
            merge10(t2, other);
            a2 += __shfl_xor_sync(0xFFFFFFFFu, a2, off);
        }

        if (lid == 0) {
            const bool h1 = hasF[0] != 0, h2 = hasF[1] != 0, h3 = hasF[2] != 0;
            const bool gt4 = !(h1 | h2 | h3);
            bool found = false;
            float corr = 0.0f;
            float multf[TOPK];
            int   idxs[TOPK];
#pragma unroll
            for (int r = 0; r < TOPK; ++r) {
                int j = (int)(~(unsigned)t2[r]);
                idxs[r] = j;
                int wl = wl_map[j];
                bool in_map = wl > 0;
                bool in_gt = (wl == 1 && h1) || (wl == 2 && h2) ||
                             (wl == 3 && h3) || (wl == 4 && gt4);
                float f = (in_map && gt4) ? 0.5f : 1.0f;
                if (in_map && !in_gt && !found) f *= 2.0f;
                multf[r] = f;
                found = found || (in_map && in_gt);
            }
            const float extra = found ? 1.0f : 2.0f;
#pragma unroll
            for (int r = 0; r < TOPK; ++r) {
                float f = multf[r] * extra;
                if (f != 1.0f) {
                    int j = idxs[r];
                    corr += elem_bw(xr[j], yr[j]) * (f - 1.0f);
                }
            }
            atomicAdd(out, -(a2 + corr));
        }
    }
}

extern "C" void kernel_launch(void* const* d_in, const int* in_sizes, int n_in,
                              void* d_out, int out_size)
{
    const float* x           = (const float*)d_in[0];
    const float* y           = (const float*)d_in[1];
    const int*   compost_idx = (const int*)d_in[2];
    const int*   recycle_idx = (const int*)d_in[3];
    const int*   donate_idx  = (const int*)d_in[4];
    const int*   wl_map      = (const int*)d_in[5];
    float*       out         = (float*)d_out;

    zero_out_kernel<<<1, 1>>>(out);
    asl_loss_kernel<<<NB, TPB>>>(x, y, compost_idx, recycle_idx, donate_idx,
                                 wl_map, out);
}

// round 3
// speedup vs baseline: 4.1794x; 1.6760x over previous
#include <cuda_runtime.h>
#include <cstdint>
#include <math_constants.h>

#define NB 2048
#define NC 9605
#define TPB 256
#define WPB 8          // warps (rows) per block
#define TOPK 10
#define FULL 0xFFFFFFFFu

typedef unsigned long long u64;

__global__ void zero_out_kernel(float* out) { out[0] = 0.0f; }

__device__ __forceinline__ unsigned ordkey(float v) {
    unsigned u = __float_as_uint(v);
    return (int)u < 0 ? ~u : (u | 0x80000000u);
}

// base*w for one element (gamma_pos=1, gamma_neg=4, clip=0.05), branchless
__device__ __forceinline__ float elem_bw(float xv, float yv) {
    float e  = __expf(-xv);
    float r  = __fdividef(1.0f, 1.0f + e);      // sigmoid
    float pn = fminf(1.05f - r, 1.0f);          // xs_neg (>= 0.05)
    bool  yp = yv != 0.0f;
    float arg = yp ? fmaxf(r, 1e-8f) : pn;
    float base = __logf(arg);                   // one LG2 for both paths
    float t  = fmaxf(r - 0.05f, 0.0f);          // 1 - xs_neg
    float t2 = t * t;
    float w  = yp ? (1.0f - r) : (t2 * t2);
    return base * w;
}

// warp-distributed sorted insert: lane l<10 holds rank-l key (descending)
__device__ __forceinline__ void coop_insert(u64& kreg, int lid, u64 bk) {
    bool p = (lid < TOPK) && (bk > kreg);
    unsigned pb = __ballot_sync(FULL, p);
    if (pb) {
        int pos = __ffs(pb) - 1;
        u64 up = __shfl_up_sync(FULL, kreg, 1);
        if (lid < TOPK && lid >= pos) kreg = (lid == pos) ? bk : up;
    }
}

__device__ __forceinline__ float thresh_from(u64 kreg) {
    u64 k9 = __shfl_sync(FULL, kreg, TOPK - 1);
    if (k9 == 0ull) return -CUDART_INF_F;
    unsigned hi = (unsigned)(k9 >> 32);
    unsigned u = (hi & 0x80000000u) ? (hi & 0x7FFFFFFFu) : ~hi;
    return __uint_as_float(u);
}

__global__ __launch_bounds__(TPB)
void asl_loss_kernel(const float* __restrict__ x, const float* __restrict__ y,
                     const int* __restrict__ compost_idx,
                     const int* __restrict__ recycle_idx,
                     const int* __restrict__ donate_idx,
                     const int* __restrict__ wl_map,
                     float* __restrict__ out)
{
    const int lid = threadIdx.x & 31;
    const int row = blockIdx.x * WPB + (threadIdx.x >> 5);
    const float* __restrict__ xr = x + (size_t)row * NC;
    const float* __restrict__ yr = y + (size_t)row * NC;

    u64 kreg = 0ull;                 // distributed top-10 (lanes 0..9)
    float tf = -CUDART_INF_F;        // 10th-largest x so far (warp-uniform)
    float acc = 0.0f;

    // float4 alignment fixup (row base rotates mod 16B since NC*4 % 16 == 4)
    const int mis = (int)(((uintptr_t)xr & 15u) >> 2);
    const int pre = (4 - mis) & 3;
    const int n4  = (NC - pre) >> 2;
    const int tail_start = pre + (n4 << 2);
    const int tail = NC - tail_start;

    const float4* __restrict__ x4 = (const float4*)(xr + pre);
    const float4* __restrict__ y4 = (const float4*)(yr + pre);

    for (int kb = 0; kb < n4; kb += 32) {
        int k = kb + lid;
        bool valid = k < n4;
        int kk = valid ? k : (n4 - 1);
        float4 xv = x4[kk];
        float4 yv = y4[kk];
        if (!valid) {
            xv.x = xv.y = xv.z = xv.w = -CUDART_INF_F;
            yv.x = yv.y = yv.z = yv.w = 0.0f;
        }
        acc += elem_bw(xv.x, yv.x);
        acc += elem_bw(xv.y, yv.y);
        acc += elem_bw(xv.z, yv.z);
        acc += elem_bw(xv.w, yv.w);

        float m = fmaxf(fmaxf(xv.x, xv.y), fmaxf(xv.z, xv.w));
        unsigned bal = __ballot_sync(FULL, m >= tf);
        if (bal) {
            int cbase = pre + (k << 2);
            const float xs[4] = {xv.x, xv.y, xv.z, xv.w};
#pragma unroll
            for (int j = 0; j < 4; ++j) {
                unsigned bj = __ballot_sync(FULL, xs[j] >= tf);
                if (bj) {
                    u64 myk = ((u64)ordkey(xs[j]) << 32)
                            | (unsigned)(~(unsigned)(cbase + j));
                    while (bj) {
                        int s = __ffs(bj) - 1;
                        bj &= bj - 1;
                        u64 bk = __shfl_sync(FULL, myk, s);
                        coop_insert(kreg, lid, bk);
                    }
                }
            }
            tf = thresh_from(kreg);
        }
    }

    // pre + tail scalars (<= 7 elements), processed cooperatively
    {
        int c = -1;
        if (lid < pre) c = lid;
        else if (lid >= 8 && lid < 8 + tail) c = tail_start + (lid - 8);
        float xsv = -CUDART_INF_F, ysv = 0.0f;
        if (c >= 0) { xsv = xr[c]; ysv = yr[c]; }
        acc += elem_bw(xsv, ysv);
        unsigned bs = __ballot_sync(FULL, xsv >= tf);
        if (bs) {
            u64 myk = ((u64)ordkey(xsv) << 32) | (unsigned)(~(unsigned)c);
            while (bs) {
                int s = __ffs(bs) - 1;
                bs &= bs - 1;
                u64 bk = __shfl_sync(FULL, myk, s);
                coop_insert(kreg, lid, bk);
            }
        }
    }

    // warp sum reduction
#pragma unroll
    for (int off = 16; off >= 1; off >>= 1)
        acc += __shfl_xor_sync(FULL, acc, off);

    // per-row whitelist-group presence flags
    bool v1 = false, v2 = false, v3 = false;
    if (lid < 30) v1 = yr[compost_idx[lid]] > 0.0f;
#pragma unroll
    for (int i = 0; i < 3; ++i) {
        int t = lid + 32 * i;
        if (t < 70) {
            v2 |= yr[recycle_idx[t]] > 0.0f;
            v3 |= yr[donate_idx[t]]  > 0.0f;
        }
    }
    bool h1 = __ballot_sync(FULL, v1) != 0;
    bool h2 = __ballot_sync(FULL, v2) != 0;
    bool h3 = __ballot_sync(FULL, v3) != 0;
    const bool gt4 = !(h1 | h2 | h3);

    // sequential 10-rank whitelist scan (all lanes compute redundantly)
    bool found = false;
    float multf[TOPK];
    int   idxs[TOPK];
#pragma unroll
    for (int r = 0; r < TOPK; ++r) {
        u64 kr = __shfl_sync(FULL, kreg, r);
        int j = (int)(~(unsigned)kr);
        idxs[r] = j;
        int wl = wl_map[j];
        bool in_map = wl > 0;
        bool in_gt = (wl == 1 && h1) || (wl == 2 && h2) ||
                     (wl == 3 && h3) || (wl == 4 && gt4);
        float f = (in_map && gt4) ? 0.5f : 1.0f;
        if (in_map && !in_gt && !found) f *= 2.0f;
        multf[r] = f;
        found = found || (in_map && in_gt);
    }
    const float extra = found ? 1.0f : 2.0f;
    float corr = 0.0f;
#pragma unroll
    for (int r = 0; r < TOPK; ++r) {
        float f = multf[r] * extra;
        if (f != 1.0f) {
            int j = idxs[r];
            corr += elem_bw(xr[j], yr[j]) * (f - 1.0f);
        }
    }

    if (lid == 0) atomicAdd(out, -(acc + corr));
}

extern "C" void kernel_launch(void* const* d_in, const int* in_sizes, int n_in,
                              void* d_out, int out_size)
{
    const float* x           = (const float*)d_in[0];
    const float* y           = (const float*)d_in[1];
    const int*   compost_idx = (const int*)d_in[2];
    const int*   recycle_idx = (const int*)d_in[3];
    const int*   donate_idx  = (const int*)d_in[4];
    const int*   wl_map      = (const int*)d_in[5];
    float*       out         = (float*)d_out;

    zero_out_kernel<<<1, 1>>>(out);
    asl_loss_kernel<<<NB / WPB, TPB>>>(x, y, compost_idx, recycle_idx,
                                       donate_idx, wl_map, out);
}

// round 4
// speedup vs baseline: 4.4580x; 1.0666x over previous
#include <cuda_runtime.h>
#include <cstdint>
#include <math_constants.h>

#define NB 2048
#define NC 9605
#define WPR 4           // warps per row
#define TPB (WPR * 32)
#define TOPK 10
#define FULL 0xFFFFFFFFu

typedef unsigned long long u64;

__global__ void zero_out_kernel(float* out) { out[0] = 0.0f; }

__device__ __forceinline__ unsigned ordkey(float v) {
    unsigned u = __float_as_uint(v);
    return (int)u < 0 ? ~u : (u | 0x80000000u);
}

// base*w for one element (gamma_pos=1, gamma_neg=4, clip=0.05), branchless
__device__ __forceinline__ float elem_bw(float xv, float yv) {
    float e  = __expf(-xv);
    float r  = __fdividef(1.0f, 1.0f + e);      // sigmoid
    float pn = fminf(1.05f - r, 1.0f);          // xs_neg (>= 0.05)
    bool  yp = yv != 0.0f;
    float arg = yp ? fmaxf(r, 1e-8f) : pn;
    float base = __logf(arg);                   // one LG2 both paths
    float t  = fmaxf(r - 0.05f, 0.0f);          // 1 - xs_neg
    float t2 = t * t;
    float w  = yp ? (1.0f - r) : (t2 * t2);
    return base * w;
}

// warp-distributed sorted insert: lane l<10 holds rank-l key (descending)
__device__ __forceinline__ void coop_insert(u64& kreg, int lid, u64 bk) {
    bool p = (lid < TOPK) && (bk > kreg);
    unsigned pb = __ballot_sync(FULL, p);
    if (pb) {
        int pos = __ffs(pb) - 1;
        u64 up = __shfl_up_sync(FULL, kreg, 1);
        if (lid < TOPK && lid >= pos) kreg = (lid == pos) ? bk : up;
    }
}

__device__ __forceinline__ float thresh_from(u64 kreg) {
    u64 k9 = __shfl_sync(FULL, kreg, TOPK - 1);
    if (k9 == 0ull) return -CUDART_INF_F;
    unsigned hi = (unsigned)(k9 >> 32);
    unsigned u = (hi & 0x80000000u) ? (hi & 0x7FFFFFFFu) : ~hi;
    return __uint_as_float(u);
}

__global__ __launch_bounds__(TPB)
void asl_loss_kernel(const float* __restrict__ x, const float* __restrict__ y,
                     const int* __restrict__ compost_idx,
                     const int* __restrict__ recycle_idx,
                     const int* __restrict__ donate_idx,
                     const int* __restrict__ wl_map,
                     float* __restrict__ out)
{
    const int tid = threadIdx.x;
    const int lid = tid & 31;
    const int wid = tid >> 5;
    const int row = blockIdx.x;
    const float* __restrict__ xr = x + (size_t)row * NC;
    const float* __restrict__ yr = y + (size_t)row * NC;

    __shared__ int  hasF[3];
    __shared__ u64  skeys[WPR][TOPK];
    __shared__ float sacc[WPR];

    if (tid < 3) hasF[tid] = 0;
    __syncthreads();
    // whitelist presence flags, block-cooperative (benign races, write only 1)
    if (tid < 30)                    { if (yr[compost_idx[tid]]      > 0.0f) hasF[0] = 1; }
    if (tid >= 32 && tid < 102)      { if (yr[recycle_idx[tid - 32]] > 0.0f) hasF[1] = 1; }
    {
        int t = tid - 58;  // threads 58..127 -> donate 0..69
        if (t >= 0 && t < 70)        { if (yr[donate_idx[t]]         > 0.0f) hasF[2] = 1; }
    }

    u64 kreg = 0ull;
    float tf = -CUDART_INF_F;
    float acc = 0.0f;

    const int mis = (int)(((uintptr_t)xr & 15u) >> 2);
    const int pre = (4 - mis) & 3;
    const int n4  = (NC - pre) >> 2;
    const int tail_start = pre + (n4 << 2);
    const int tail = NC - tail_start;

    const float4* __restrict__ x4 = (const float4*)(xr + pre);
    const float4* __restrict__ y4 = (const float4*)(yr + pre);

    // warp w handles 32-quad chunks starting at w*32, stride 128 quads
    for (int kb = wid * 32; kb < n4; kb += WPR * 32) {
        int k = kb + lid;
        bool valid = k < n4;
        int kk = valid ? k : (n4 - 1);
        float4 xv = x4[kk];
        float4 yv = y4[kk];
        if (!valid) {
            xv.x = xv.y = xv.z = xv.w = -CUDART_INF_F;
            yv.x = yv.y = yv.z = yv.w = 0.0f;
        }
        acc += elem_bw(xv.x, yv.x);
        acc += elem_bw(xv.y, yv.y);
        acc += elem_bw(xv.z, yv.z);
        acc += elem_bw(xv.w, yv.w);

        float m = fmaxf(fmaxf(xv.x, xv.y), fmaxf(xv.z, xv.w));
        unsigned bal = __ballot_sync(FULL, m >= tf);
        if (bal) {
            int cbase = pre + (k << 2);
            const float xs[4] = {xv.x, xv.y, xv.z, xv.w};
#pragma unroll
            for (int j = 0; j < 4; ++j) {
                unsigned bj = __ballot_sync(FULL, xs[j] >= tf);
                if (bj) {
                    u64 myk = ((u64)ordkey(xs[j]) << 32)
                            | (unsigned)(~(unsigned)(cbase + j));
                    while (bj) {
                        int s = __ffs(bj) - 1;
                        bj &= bj - 1;
                        u64 bk = __shfl_sync(FULL, myk, s);
                        coop_insert(kreg, lid, bk);
                    }
                }
            }
            tf = thresh_from(kreg);
        }
    }

    // pre + tail scalars (<=7 elems), warp 0 handles cooperatively
    if (wid == 0) {
        int c = -1;
        if (lid < pre) c = lid;
        else if (lid >= 8 && lid < 8 + tail) c = tail_start + (lid - 8);
        float xsv = -CUDART_INF_F, ysv = 0.0f;
        if (c >= 0) { xsv = xr[c]; ysv = yr[c]; }
        acc += elem_bw(xsv, ysv);
        unsigned bs = __ballot_sync(FULL, xsv >= tf);
        if (bs) {
            u64 myk = ((u64)ordkey(xsv) << 32) | (unsigned)(~(unsigned)c);
            while (bs) {
                int s = __ffs(bs) - 1;
                bs &= bs - 1;
                u64 bk = __shfl_sync(FULL, myk, s);
                coop_insert(kreg, lid, bk);
            }
        }
    }

    // per-warp sum reduce + stash partials
#pragma unroll
    for (int off = 16; off >= 1; off >>= 1)
        acc += __shfl_xor_sync(FULL, acc, off);
    if (lid == 0) sacc[wid] = acc;
    if (lid < TOPK) skeys[wid][lid] = kreg;
    __syncthreads();

    if (wid == 0) {
        // merge other warps' top-10 lists (30 broadcast inserts)
#pragma unroll
        for (int w = 1; w < WPR; ++w) {
#pragma unroll
            for (int r = 0; r < TOPK; ++r) {
                u64 bk = skeys[w][r];
                if (bk > __shfl_sync(FULL, kreg, TOPK - 1))
                    coop_insert(kreg, lid, bk);
            }
        }
        float a2 = sacc[0] + sacc[1] + sacc[2] + sacc[3];

        const bool h1 = hasF[0] != 0, h2 = hasF[1] != 0, h3 = hasF[2] != 0;
        const bool gt4 = !(h1 | h2 | h3);

        // sequential 10-rank whitelist scan (all lanes redundantly)
        bool found = false;
        float multf[TOPK];
        int   idxs[TOPK];
#pragma unroll
        for (int r = 0; r < TOPK; ++r) {
            u64 kr = __shfl_sync(FULL, kreg, r);
            int j = (int)(~(unsigned)kr);
            idxs[r] = j;
            int wl = wl_map[j];
            bool in_map = wl > 0;
            bool in_gt = (wl == 1 && h1) || (wl == 2 && h2) ||
                         (wl == 3 && h3) || (wl == 4 && gt4);
            float f = (in_map && gt4) ? 0.5f : 1.0f;
            if (in_map && !in_gt && !found) f *= 2.0f;
            multf[r] = f;
            found = found || (in_map && in_gt);
        }
        const float extra = found ? 1.0f : 2.0f;
        float corr = 0.0f;
#pragma unroll
        for (int r = 0; r < TOPK; ++r) {
            float f = multf[r] * extra;
            if (f != 1.0f) {
                int j = idxs[r];
                corr += elem_bw(xr[j], yr[j]) * (f - 1.0f);
            }
        }
        if (lid == 0) atomicAdd(out, -(a2 + corr));
    }
}

extern "C" void kernel_launch(void* const* d_in, const int* in_sizes, int n_in,
                              void* d_out, int out_size)
{
    const float* x           = (const float*)d_in[0];
    const float* y           = (const float*)d_in[1];
    const int*   compost_idx = (const int*)d_in[2];
    const int*   recycle_idx = (const int*)d_in[3];
    const int*   donate_idx  = (const int*)d_in[4];
    const int*   wl_map      = (const int*)d_in[5];
    float*       out         = (float*)d_out;

    zero_out_kernel<<<1, 1>>>(out);
    asl_loss_kernel<<<NB, TPB>>>(x, y, compost_idx, recycle_idx,
                                 donate_idx, wl_map, out);
}

// round 5
// speedup vs baseline: 6.3324x; 1.4205x over previous
#include <cuda_runtime.h>
#include <cstdint>
#include <math_constants.h>

#define NB 2048
#define NC 9605
#define WPR 4           // warps per row
#define TPB (WPR * 32)
#define TOPK 10
#define FULL 0xFFFFFFFFu

typedef unsigned long long u64;

__global__ void zero_out_kernel(float* out) { out[0] = 0.0f; }

__device__ __forceinline__ unsigned ordkey(float v) {
    unsigned u = __float_as_uint(v);
    return (int)u < 0 ? ~u : (u | 0x80000000u);
}

// base*w (gamma_pos=1, gamma_neg=4, clip=0.05); selects via fmaf blends (y in {0,1})
__device__ __forceinline__ float elem_bw(float xv, float yv) {
    float e    = exp2f(-1.44269504f * xv);
    float r    = __fdividef(1.0f, 1.0f + e);   // sigmoid
    float t    = fmaxf(r - 0.05f, 0.0f);       // 1 - xs_neg
    float pn   = 1.0f - t;                     // xs_neg = min(1.05-r, 1)
    float argp = fmaxf(r, 1e-8f);
    float arg  = fmaf(yv, argp - pn, pn);      // y ? argp : pn
    float lg   = __logf(arg);
    float t2   = t * t;
    float t4   = t2 * t2;
    float w    = fmaf(yv, (1.0f - r) - t4, t4); // y ? (1-r) : t^4
    return lg * w;
}

// warp-distributed sorted insert: lane l<10 holds rank-l key (descending)
__device__ __forceinline__ void coop_insert(u64& kreg, int lid, u64 bk) {
    bool p = (lid < TOPK) && (bk > kreg);
    unsigned pb = __ballot_sync(FULL, p);
    if (pb) {
        int pos = __ffs(pb) - 1;
        u64 up = __shfl_up_sync(FULL, kreg, 1);
        if (lid < TOPK && lid >= pos) kreg = (lid == pos) ? bk : up;
    }
}

__device__ __forceinline__ float thresh_from(u64 kreg) {
    u64 k9 = __shfl_sync(FULL, kreg, TOPK - 1);
    if (k9 == 0ull) return -CUDART_INF_F;
    unsigned hi = (unsigned)(k9 >> 32);
    unsigned u = (hi & 0x80000000u) ? (hi & 0x7FFFFFFFu) : ~hi;
    return __uint_as_float(u);
}

// process one quad's candidates (x >= tf) with exact inserts
__device__ __forceinline__ void take_quad(u64& kreg, int lid, float tf,
                                          const float4& xv, int cbase) {
    const float xs[4] = {xv.x, xv.y, xv.z, xv.w};
#pragma unroll
    for (int j = 0; j < 4; ++j) {
        unsigned bj = __ballot_sync(FULL, xs[j] >= tf);
        if (bj) {
            u64 myk = ((u64)ordkey(xs[j]) << 32)
                    | (unsigned)(~(unsigned)(cbase + j));
            while (bj) {
                int s = __ffs(bj) - 1;
                bj &= bj - 1;
                u64 bk = __shfl_sync(FULL, myk, s);
                coop_insert(kreg, lid, bk);
            }
        }
    }
}

__global__ __launch_bounds__(TPB)
void asl_loss_kernel(const float* __restrict__ x, const float* __restrict__ y,
                     const int* __restrict__ compost_idx,
                     const int* __restrict__ recycle_idx,
                     const int* __restrict__ donate_idx,
                     const int* __restrict__ wl_map,
                     float* __restrict__ out)
{
    const int tid = threadIdx.x;
    const int lid = tid & 31;
    const int wid = tid >> 5;
    const int row = blockIdx.x;
    const float* __restrict__ xr = x + (size_t)row * NC;
    const float* __restrict__ yr = y + (size_t)row * NC;

    __shared__ int   hasF[3];
    __shared__ u64   skeys[WPR][TOPK];
    __shared__ float sacc[WPR];

    if (tid < 3) hasF[tid] = 0;
    __syncthreads();
    if (tid < 30)               { if (yr[compost_idx[tid]]      > 0.0f) hasF[0] = 1; }
    if (tid >= 32 && tid < 102) { if (yr[recycle_idx[tid - 32]] > 0.0f) hasF[1] = 1; }
    { int t = tid - 58; if (t >= 0 && t < 70) { if (yr[donate_idx[t]] > 0.0f) hasF[2] = 1; } }

    const int mis = (int)(((uintptr_t)xr & 15u) >> 2);
    const int pre = (4 - mis) & 3;
    const int n4  = (NC - pre) >> 2;
    const int tail_start = pre + (n4 << 2);
    const int tail = NC - tail_start;

    const float4* __restrict__ x4 = (const float4*)(xr + pre);
    const float4* __restrict__ y4 = (const float4*)(yr + pre);

    u64 kreg = 0ull;
    float acc0 = 0.0f, acc1 = 0.0f;

    // ---- threshold seed: 10th largest of the 32 lane max-of-8 over first chunk
    float tf;
    {
        float4 xa = x4[wid * 64 + lid];
        float4 xb = x4[wid * 64 + 32 + lid];
        float m = fmaxf(fmaxf(fmaxf(xa.x, xa.y), fmaxf(xa.z, xa.w)),
                        fmaxf(fmaxf(xb.x, xb.y), fmaxf(xb.z, xb.w)));
        // ascending bitonic sort of 32 floats across the warp
#pragma unroll
        for (int k = 2; k <= 32; k <<= 1) {
#pragma unroll
            for (int j = k >> 1; j > 0; j >>= 1) {
                float o = __shfl_xor_sync(FULL, m, j);
                bool asc = ((lid & k) == 0);
                bool low = ((lid & j) == 0);
                float mn = fminf(m, o), mx = fmaxf(m, o);
                m = (asc == low) ? mn : mx;
            }
        }
        tf = __shfl_sync(FULL, m, 32 - TOPK);   // 10th largest (>=10 elems >= tf)
    }

    // ---- main loop: 8 elements per lane per iteration
    for (int kb = wid * 64; kb < n4; kb += WPR * 64) {
        int ka = kb + lid;
        int kc = kb + 32 + lid;
        bool va = ka < n4, vb = kc < n4;
        int kca = va ? ka : 0, kcb = vb ? kc : 0;
        float4 xa = x4[kca];
        float4 ya = y4[kca];
        float4 xb = x4[kcb];
        float4 yb = y4[kcb];
        if (!va) { xa.x = xa.y = xa.z = xa.w = -CUDART_INF_F;
                   ya.x = ya.y = ya.z = ya.w = 0.0f; }
        if (!vb) { xb.x = xb.y = xb.z = xb.w = -CUDART_INF_F;
                   yb.x = yb.y = yb.z = yb.w = 0.0f; }

        acc0 += elem_bw(xa.x, ya.x);
        acc1 += elem_bw(xa.y, ya.y);
        acc0 += elem_bw(xa.z, ya.z);
        acc1 += elem_bw(xa.w, ya.w);
        acc0 += elem_bw(xb.x, yb.x);
        acc1 += elem_bw(xb.y, yb.y);
        acc0 += elem_bw(xb.z, yb.z);
        acc1 += elem_bw(xb.w, yb.w);

        float ma = fmaxf(fmaxf(xa.x, xa.y), fmaxf(xa.z, xa.w));
        float mb = fmaxf(fmaxf(xb.x, xb.y), fmaxf(xb.z, xb.w));
        if (__ballot_sync(FULL, fmaxf(ma, mb) >= tf)) {
            if (__ballot_sync(FULL, ma >= tf))
                take_quad(kreg, lid, tf, xa, pre + (ka << 2));
            if (__ballot_sync(FULL, mb >= tf))
                take_quad(kreg, lid, tf, xb, pre + (kc << 2));
            float nt = thresh_from(kreg);
            tf = fmaxf(tf, nt);
        }
    }

    // pre + tail scalars (<=7 elems), warp 0 cooperatively
    if (wid == 0) {
        int c = -1;
        if (lid < pre) c = lid;
        else if (lid >= 8 && lid < 8 + tail) c = tail_start + (lid - 8);
        float xsv = -CUDART_INF_F, ysv = 0.0f;
        if (c >= 0) { xsv = xr[c]; ysv = yr[c]; }
        acc0 += elem_bw(xsv, ysv);
        unsigned bs = __ballot_sync(FULL, xsv >= tf);
        if (bs) {
            u64 myk = ((u64)ordkey(xsv) << 32) | (unsigned)(~(unsigned)c);
            while (bs) {
                int s = __ffs(bs) - 1;
                bs &= bs - 1;
                u64 bk = __shfl_sync(FULL, myk, s);
                coop_insert(kreg, lid, bk);
            }
        }
    }

    float acc = acc0 + acc1;
#pragma unroll
    for (int off = 16; off >= 1; off >>= 1)
        acc += __shfl_xor_sync(FULL, acc, off);
    if (lid == 0) sacc[wid] = acc;
    if (lid < TOPK) skeys[wid][lid] = kreg;
    __syncthreads();

    if (wid == 0) {
#pragma unroll
        for (int w = 1; w < WPR; ++w) {
#pragma unroll
            for (int r = 0; r < TOPK; ++r) {
                u64 bk = skeys[w][r];
                if (bk > __shfl_sync(FULL, kreg, TOPK - 1))
                    coop_insert(kreg, lid, bk);
            }
        }
        float a2 = sacc[0] + sacc[1] + sacc[2] + sacc[3];

        const bool h1 = hasF[0] != 0, h2 = hasF[1] != 0, h3 = hasF[2] != 0;
        const bool gt4 = !(h1 | h2 | h3);

        bool found = false;
        float multf[TOPK];
        int   idxs[TOPK];
#pragma unroll
        for (int r = 0; r < TOPK; ++r) {
            u64 kr = __shfl_sync(FULL, kreg, r);
            int j = (int)(~(unsigned)kr);
            idxs[r] = j;
            int wl = wl_map[j];
            bool in_map = wl > 0;
            bool in_gt = (wl == 1 && h1) || (wl == 2 && h2) ||
                         (wl == 3 && h3) || (wl == 4 && gt4);
            float f = (in_map && gt4) ? 0.5f : 1.0f;
            if (in_map && !in_gt && !found) f *= 2.0f;
            multf[r] = f;
            found = found || (in_map && in_gt);
        }
        const float extra = found ? 1.0f : 2.0f;
        float corr = 0.0f;
#pragma unroll
        for (int r = 0; r < TOPK; ++r) {
            float f = multf[r] * extra;
            if (f != 1.0f) {
                int j = idxs[r];
                corr += elem_bw(xr[j], yr[j]) * (f - 1.0f);
            }
        }
        if (lid == 0) atomicAdd(out, -(a2 + corr));
    }
}

extern "C" void kernel_launch(void* const* d_in, const int* in_sizes, int n_in,
                              void* d_out, int out_size)
{
    const float* x           = (const float*)d_in[0];
    const float* y           = (const float*)d_in[1];
    const int*   compost_idx = (const int*)d_in[2];
    const int*   recycle_idx = (const int*)d_in[3];
    const int*   donate_idx  = (const int*)d_in[4];
    const int*   wl_map      = (const int*)d_in[5];
    float*       out         = (float*)d_out;

    zero_out_kernel<<<1, 1>>>(out);
    asl_loss_kernel<<<NB, TPB>>>(x, y, compost_idx, recycle_idx,
                                 donate_idx, wl_map, out);
}